// round 1
// baseline (speedup 1.0000x reference)
#include <cuda_runtime.h>
#include <cstdint>

#define DD 1024
#define HH 4096
#define EE 8
#define TT 4096
#define RR (TT*2)          // 8192 routed (token,slot) rows
#define BM 128
#define BN 128
#define BKQ 16
#define RP (RR + EE*BM)    // 9216 padded rows upper bound

// ---------------- scratch (device globals; no allocation) ----------------
__device__ float g_H[(size_t)RP * HH];   // hidden after gelu
__device__ float g_Y[(size_t)RP * DD];   // expert outputs
__device__ float g_topw[TT * 2];
__device__ int   g_topi[TT * 2];
__device__ int   g_rows[TT * 2];         // packed row index per (token,slot)
__device__ int   g_perm[RP];             // packed row -> token
__device__ int   g_cnt[EE];
__device__ int   g_poff[EE + 1];
__device__ int   g_cur[EE];

// ---------------- helpers ----------------
__device__ __forceinline__ float to_tf32(float x) {
    uint32_t r;
    asm("cvt.rna.tf32.f32 %0, %1;" : "=r"(r) : "f"(x));
    return __uint_as_float(r);
}

__device__ __forceinline__ void mma_tf32(float* d,
                                         uint32_t a0, uint32_t a1, uint32_t a2, uint32_t a3,
                                         uint32_t b0, uint32_t b1) {
    asm volatile("mma.sync.aligned.m16n8k8.row.col.f32.tf32.tf32.f32 "
                 "{%0,%1,%2,%3}, {%4,%5,%6,%7}, {%8,%9}, {%0,%1,%2,%3};"
                 : "+f"(d[0]), "+f"(d[1]), "+f"(d[2]), "+f"(d[3])
                 : "r"(a0), "r"(a1), "r"(a2), "r"(a3), "r"(b0), "r"(b1));
}

__device__ __forceinline__ float gelu_exact(float v) {
    return 0.5f * v * (1.0f + erff(v * 0.70710678118654752440f));
}

__device__ __forceinline__ uint32_t f2u(float x) { return __float_as_uint(x); }

// ---------------- kernels ----------------
__global__ void init_kernel() {
    if (threadIdx.x < EE) g_cnt[threadIdx.x] = 0;
}

// one warp per token: logits -> softmax -> top2 -> counts
__global__ void router_kernel(const float* __restrict__ x,
                              const float* __restrict__ Wr,
                              const float* __restrict__ br) {
    __shared__ float sWr[EE * DD];                       // 32 KB
    int tid = threadIdx.x;
    for (int i = tid; i < EE * DD / 4; i += blockDim.x)
        ((float4*)sWr)[i] = ((const float4*)Wr)[i];
    __syncthreads();

    int warp = (blockIdx.x * blockDim.x + tid) >> 5;     // token id, grid sized exactly
    int lane = tid & 31;
    const float4* xv = (const float4*)(x + (size_t)warp * DD);

    float acc[EE];
#pragma unroll
    for (int e = 0; e < EE; e++) acc[e] = 0.f;
#pragma unroll
    for (int i = 0; i < DD / 128; i++) {                 // 8 passes
        float4 xs = xv[lane + i * 32];
#pragma unroll
        for (int e = 0; e < EE; e++) {
            float4 w = ((const float4*)(sWr + e * DD))[lane + i * 32];
            acc[e] += xs.x * w.x + xs.y * w.y + xs.z * w.z + xs.w * w.w;
        }
    }
#pragma unroll
    for (int e = 0; e < EE; e++)
#pragma unroll
        for (int off = 16; off > 0; off >>= 1)
            acc[e] += __shfl_xor_sync(0xffffffffu, acc[e], off);

    if (lane == 0) {
        float lg[EE];
        float m = -1e30f;
#pragma unroll
        for (int e = 0; e < EE; e++) { lg[e] = acc[e] + br[e]; m = fmaxf(m, lg[e]); }
        float s = 0.f;
#pragma unroll
        for (int e = 0; e < EE; e++) { lg[e] = expf(lg[e] - m); s += lg[e]; }
        float inv = 1.f / s;
        int i0 = 0; float v0 = lg[0];
#pragma unroll
        for (int e = 1; e < EE; e++) if (lg[e] > v0) { v0 = lg[e]; i0 = e; }
        int i1 = -1; float v1 = -1.f;
#pragma unroll
        for (int e = 0; e < EE; e++) if (e != i0 && lg[e] > v1) { v1 = lg[e]; i1 = e; }
        g_topi[2 * warp]     = i0;
        g_topi[2 * warp + 1] = i1;
        g_topw[2 * warp]     = v0 * inv;
        g_topw[2 * warp + 1] = v1 * inv;
        atomicAdd(&g_cnt[i0], 1);
        atomicAdd(&g_cnt[i1], 1);
    }
}

__global__ void offsets_kernel() {
    if (threadIdx.x == 0) {
        int off = 0;
        for (int e = 0; e < EE; e++) {
            g_poff[e] = off;
            g_cur[e]  = off;
            off += ((g_cnt[e] + BM - 1) / BM) * BM;      // pad to tile
        }
        g_poff[EE] = off;
    }
}

__global__ void scatter_kernel() {
    int idx = blockIdx.x * blockDim.x + threadIdx.x;
    if (idx >= 2 * TT) return;
    int e = g_topi[idx];
    int pos = atomicAdd(&g_cur[e], 1);
    g_rows[idx] = pos;
    g_perm[pos] = idx >> 1;
}

// C[M,N] = act(A[M,K] @ B_e[N,K]^T + bias_e)   (tf32 tensor cores)
// PHASE1: A = x gathered via perm, C = g_H with gelu. else: A = g_H, C = g_Y.
template <bool PHASE1>
__global__ __launch_bounds__(256, 1)
void gemm_tf32(const float* __restrict__ Axp,
               const float* __restrict__ Bw,
               const float* __restrict__ bias) {
    constexpr int N = PHASE1 ? HH : DD;
    constexpr int K = PHASE1 ? DD : HH;
    constexpr int NITER = K / BKQ;

    __shared__ float sA[2][BM * BKQ];
    __shared__ float sB[2][BN * BKQ];

    const int m0 = blockIdx.y * BM;
    const int n0 = blockIdx.x * BN;

    const int tot = g_poff[EE];
    if (m0 >= tot) return;
    int e = 0;
#pragma unroll
    for (int i = 0; i < EE; i++) if (m0 >= g_poff[i + 1]) e = i + 1;

    const int tid  = threadIdx.x;
    const int warp = tid >> 5, lane = tid & 31;
    const int g = lane >> 2, t = lane & 3;
    const int wr = warp >> 2, wc = warp & 3;             // 2x4 warp grid

    // staging map: each thread owns one row (tid>>1) and two float4 columns
    const int rA  = tid >> 1;
    const int c4b = (tid & 1) * 2;

    const float* A = PHASE1 ? Axp : g_H;
    size_t rowA;
    if (PHASE1) rowA = (size_t)g_perm[m0 + rA] * (size_t)K;  // gather token row
    else        rowA = (size_t)(m0 + rA) * (size_t)K;
    const float* pA = A + rowA + c4b * 4;
    const float* pB = Bw + ((size_t)e * N + n0 + rA) * (size_t)K + c4b * 4;
    const float* biasp = bias + (size_t)e * N;

    float acc[4][4][4];
#pragma unroll
    for (int i = 0; i < 4; i++)
#pragma unroll
        for (int j = 0; j < 4; j++)
#pragma unroll
            for (int r = 0; r < 4; r++) acc[i][j][r] = 0.f;

    // permuted store: element (row,k) -> smem[row*16 + (k%4)*4 + k/4]
    auto sts_perm = [&](float* s, int row, int c4, float4 v) {
        float* base = s + row * BKQ + c4;
        base[0]  = to_tf32(v.x);
        base[4]  = to_tf32(v.y);
        base[8]  = to_tf32(v.z);
        base[12] = to_tf32(v.w);
    };

    float4 ra0 = *(const float4*)pA;
    float4 ra1 = *(const float4*)(pA + 4);
    float4 rb0 = *(const float4*)pB;
    float4 rb1 = *(const float4*)(pB + 4);
    sts_perm(sA[0], rA, c4b,     ra0);
    sts_perm(sA[0], rA, c4b + 1, ra1);
    sts_perm(sB[0], rA, c4b,     rb0);
    sts_perm(sB[0], rA, c4b + 1, rb1);
    __syncthreads();

    for (int it = 0; it < NITER; ++it) {
        const int cur = it & 1;
        if (it + 1 < NITER) {
            const float* qA = pA + (it + 1) * BKQ;
            const float* qB = pB + (it + 1) * BKQ;
            ra0 = *(const float4*)qA;
            ra1 = *(const float4*)(qA + 4);
            rb0 = *(const float4*)qB;
            rb1 = *(const float4*)(qB + 4);
        }

        const float* sAc = sA[cur];
        const float* sBc = sB[cur];
        float4 a_lo[4], a_hi[4], b_[4];
#pragma unroll
        for (int mt = 0; mt < 4; mt++) {
            int rm = wr * 64 + mt * 16 + g;
            a_lo[mt] = *(const float4*)(sAc + rm * BKQ + t * 4);
            a_hi[mt] = *(const float4*)(sAc + (rm + 8) * BKQ + t * 4);
        }
#pragma unroll
        for (int nt = 0; nt < 4; nt++) {
            int rn = wc * 32 + nt * 8 + g;
            b_[nt] = *(const float4*)(sBc + rn * BKQ + t * 4);
        }
#pragma unroll
        for (int mt = 0; mt < 4; mt++)
#pragma unroll
            for (int nt = 0; nt < 4; nt++) {
                mma_tf32(acc[mt][nt],
                         f2u(a_lo[mt].x), f2u(a_hi[mt].x), f2u(a_lo[mt].y), f2u(a_hi[mt].y),
                         f2u(b_[nt].x),  f2u(b_[nt].y));
                mma_tf32(acc[mt][nt],
                         f2u(a_lo[mt].z), f2u(a_hi[mt].z), f2u(a_lo[mt].w), f2u(a_hi[mt].w),
                         f2u(b_[nt].z),  f2u(b_[nt].w));
            }

        if (it + 1 < NITER) {
            const int nxt = cur ^ 1;
            sts_perm(sA[nxt], rA, c4b,     ra0);
            sts_perm(sA[nxt], rA, c4b + 1, ra1);
            sts_perm(sB[nxt], rA, c4b,     rb0);
            sts_perm(sB[nxt], rA, c4b + 1, rb1);
        }
        __syncthreads();
    }

    // epilogue
    float* C = PHASE1 ? g_H : g_Y;
    constexpr int ldc = N;
#pragma unroll
    for (int mt = 0; mt < 4; mt++) {
        int rm = m0 + wr * 64 + mt * 16 + g;
#pragma unroll
        for (int nt = 0; nt < 4; nt++) {
            int c = n0 + wc * 32 + nt * 8 + 2 * t;
            float b0v = biasp[c], b1v = biasp[c + 1];
            float v00 = acc[mt][nt][0] + b0v;
            float v01 = acc[mt][nt][1] + b1v;
            float v10 = acc[mt][nt][2] + b0v;
            float v11 = acc[mt][nt][3] + b1v;
            if (PHASE1) {
                v00 = gelu_exact(v00); v01 = gelu_exact(v01);
                v10 = gelu_exact(v10); v11 = gelu_exact(v11);
            }
            *(float2*)&C[(size_t)rm * ldc + c]       = make_float2(v00, v01);
            *(float2*)&C[(size_t)(rm + 8) * ldc + c] = make_float2(v10, v11);
        }
    }
}

__global__ void combine_kernel(float* __restrict__ out) {
    int tk = blockIdx.x;
    int d4 = threadIdx.x;                                // 0..255 (= DD/4)
    int r0 = g_rows[2 * tk], r1 = g_rows[2 * tk + 1];
    float w0 = g_topw[2 * tk], w1 = g_topw[2 * tk + 1];
    float4 y0 = *(const float4*)&g_Y[(size_t)r0 * DD + d4 * 4];
    float4 y1 = *(const float4*)&g_Y[(size_t)r1 * DD + d4 * 4];
    float4 o;
    o.x = w0 * y0.x + w1 * y1.x;
    o.y = w0 * y0.y + w1 * y1.y;
    o.z = w0 * y0.z + w1 * y1.z;
    o.w = w0 * y0.w + w1 * y1.w;
    ((float4*)out)[(size_t)tk * (DD / 4) + d4] = o;
}

// ---------------- launch ----------------
extern "C" void kernel_launch(void* const* d_in, const int* in_sizes, int n_in,
                              void* d_out, int out_size) {
    const float* x  = (const float*)d_in[0];
    const float* Wr = (const float*)d_in[1];
    const float* br = (const float*)d_in[2];
    const float* W1 = (const float*)d_in[3];
    const float* b1 = (const float*)d_in[4];
    const float* W2 = (const float*)d_in[5];
    const float* b2 = (const float*)d_in[6];
    float* out = (float*)d_out;
    (void)in_sizes; (void)n_in; (void)out_size;

    init_kernel<<<1, 32>>>();
    router_kernel<<<TT / 8, 256>>>(x, Wr, br);
    offsets_kernel<<<1, 1>>>();
    scatter_kernel<<<(2 * TT + 255) / 256, 256>>>();
    gemm_tf32<true ><<<dim3(HH / BN, RP / BM), 256>>>(x,       W1, b1);
    gemm_tf32<false><<<dim3(DD / BN, RP / BM), 256>>>(nullptr, W2, b2);
    combine_kernel<<<TT, 256>>>(out);
}

// round 3
// speedup vs baseline: 1.4149x; 1.4149x over previous
#include <cuda_runtime.h>
#include <cstdint>

#define DD 1024
#define HH 4096
#define EE 8
#define TT 4096
#define BM 128
#define BNC 256
#define BK 32
#define NS 4
#define RP 9216

// ---------------- scratch (device globals; no allocation) ----------------
__device__ float g_H[(size_t)RP * HH];      // gelu output, rna-rounded + k-permuted
__device__ float g_Y[(size_t)RP * DD];      // expert outputs (plain layout)
__device__ float g_Xc[(size_t)TT * DD];     // x, rna-rounded + k-permuted
__device__ float g_W1c[(size_t)EE * HH * DD];
__device__ float g_W2c[(size_t)EE * DD * HH];
__device__ float g_topw[TT * 2];
__device__ int   g_topi[TT * 2];
__device__ int   g_rows[TT * 2];
__device__ int   g_perm[RP];
__device__ int   g_cnt[EE];
__device__ int   g_poff[EE + 1];
__device__ int   g_cur[EE];

// ---------------- helpers ----------------
__device__ __forceinline__ uint32_t smem_u32(const void* p) {
    uint32_t a;
    asm("{ .reg .u64 t; cvta.to.shared.u64 t, %1; cvt.u32.u64 %0, t; }" : "=r"(a) : "l"(p));
    return a;
}
__device__ __forceinline__ float to_tf32(float x) {
    uint32_t r;
    asm("cvt.rna.tf32.f32 %0, %1;" : "=r"(r) : "f"(x));
    return __uint_as_float(r);
}
__device__ __forceinline__ void mma_tf32(float* d,
                                         float a0, float a1, float a2, float a3,
                                         float b0, float b1) {
    asm volatile("mma.sync.aligned.m16n8k8.row.col.f32.tf32.tf32.f32 "
                 "{%0,%1,%2,%3}, {%4,%5,%6,%7}, {%8,%9}, {%0,%1,%2,%3};"
                 : "+f"(d[0]), "+f"(d[1]), "+f"(d[2]), "+f"(d[3])
                 : "r"(__float_as_uint(a0)), "r"(__float_as_uint(a1)),
                   "r"(__float_as_uint(a2)), "r"(__float_as_uint(a3)),
                   "r"(__float_as_uint(b0)), "r"(__float_as_uint(b1)));
}
__device__ __forceinline__ float gelu_exact(float v) {
    return 0.5f * v * (1.0f + erff(v * 0.70710678118654752440f));
}
__device__ __forceinline__ void cp16(uint32_t dst, const void* src) {
    asm volatile("cp.async.cg.shared.global [%0], [%1], 16;" :: "r"(dst), "l"(src) : "memory");
}
#define CP_COMMIT() asm volatile("cp.async.commit_group;" ::: "memory")
#define CP_WAIT2()  asm volatile("cp.async.wait_group 2;" ::: "memory")
// chunk swizzle: conflict-free for both LDGSTS writes and frag reads
__device__ __forceinline__ uint32_t fsw(uint32_t g) { return ((g & 1u) << 2) | (g >> 1); }

// ---------------- small kernels ----------------
__global__ void init_kernel() {
    if (threadIdx.x < EE) g_cnt[threadIdx.x] = 0;
}

// transpose-permute + rna round: per 16-float group, out[j] = rna(in[(j%4)*4+j/4])
__global__ void convert_permute(const float* __restrict__ src, float* __restrict__ dst,
                                int ngroups) {
    int gidx = blockIdx.x * blockDim.x + threadIdx.x;
    if (gidx >= ngroups) return;
    const float4* s = (const float4*)(src + (size_t)gidx * 16);
    float4 i0 = s[0], i1 = s[1], i2 = s[2], i3 = s[3];
    float4* d = (float4*)(dst + (size_t)gidx * 16);
    d[0] = make_float4(to_tf32(i0.x), to_tf32(i1.x), to_tf32(i2.x), to_tf32(i3.x));
    d[1] = make_float4(to_tf32(i0.y), to_tf32(i1.y), to_tf32(i2.y), to_tf32(i3.y));
    d[2] = make_float4(to_tf32(i0.z), to_tf32(i1.z), to_tf32(i2.z), to_tf32(i3.z));
    d[3] = make_float4(to_tf32(i0.w), to_tf32(i1.w), to_tf32(i2.w), to_tf32(i3.w));
}

// one warp per token: logits -> softmax -> top2 -> counts; also emits g_Xc
__global__ void router_kernel(const float* __restrict__ x,
                              const float* __restrict__ Wr,
                              const float* __restrict__ br) {
    __shared__ float sWr[EE * DD];
    int tid = threadIdx.x;
    for (int i = tid; i < EE * DD / 4; i += blockDim.x)
        ((float4*)sWr)[i] = ((const float4*)Wr)[i];
    __syncthreads();

    int warp = (blockIdx.x * blockDim.x + tid) >> 5;
    int lane = tid & 31;
    const float4* xv = (const float4*)(x + (size_t)warp * DD);

    float acc[EE];
#pragma unroll
    for (int e = 0; e < EE; e++) acc[e] = 0.f;
#pragma unroll
    for (int i = 0; i < DD / 128; i++) {
        float4 xs = xv[lane + i * 32];
#pragma unroll
        for (int e = 0; e < EE; e++) {
            float4 w = ((const float4*)(sWr + e * DD))[lane + i * 32];
            acc[e] += xs.x * w.x + xs.y * w.y + xs.z * w.z + xs.w * w.w;
        }
    }
    // emit converted+permuted x row (L1-hot reload): 64 groups, 2 per lane
#pragma unroll
    for (int r = 0; r < 2; r++) {
        int grp = lane + r * 32;
        const float4* s = xv + grp * 4;
        float4 i0 = s[0], i1 = s[1], i2 = s[2], i3 = s[3];
        float4* d = (float4*)(g_Xc + (size_t)warp * DD + grp * 16);
        d[0] = make_float4(to_tf32(i0.x), to_tf32(i1.x), to_tf32(i2.x), to_tf32(i3.x));
        d[1] = make_float4(to_tf32(i0.y), to_tf32(i1.y), to_tf32(i2.y), to_tf32(i3.y));
        d[2] = make_float4(to_tf32(i0.z), to_tf32(i1.z), to_tf32(i2.z), to_tf32(i3.z));
        d[3] = make_float4(to_tf32(i0.w), to_tf32(i1.w), to_tf32(i2.w), to_tf32(i3.w));
    }
#pragma unroll
    for (int e = 0; e < EE; e++)
#pragma unroll
        for (int off = 16; off > 0; off >>= 1)
            acc[e] += __shfl_xor_sync(0xffffffffu, acc[e], off);

    if (lane == 0) {
        float lg[EE];
        float m = -1e30f;
#pragma unroll
        for (int e = 0; e < EE; e++) { lg[e] = acc[e] + br[e]; m = fmaxf(m, lg[e]); }
        float s = 0.f;
#pragma unroll
        for (int e = 0; e < EE; e++) { lg[e] = expf(lg[e] - m); s += lg[e]; }
        float inv = 1.f / s;
        int i0 = 0; float v0 = lg[0];
#pragma unroll
        for (int e = 1; e < EE; e++) if (lg[e] > v0) { v0 = lg[e]; i0 = e; }
        int i1 = -1; float v1 = -1.f;
#pragma unroll
        for (int e = 0; e < EE; e++) if (e != i0 && lg[e] > v1) { v1 = lg[e]; i1 = e; }
        g_topi[2 * warp]     = i0;
        g_topi[2 * warp + 1] = i1;
        g_topw[2 * warp]     = v0 * inv;
        g_topw[2 * warp + 1] = v1 * inv;
        atomicAdd(&g_cnt[i0], 1);
        atomicAdd(&g_cnt[i1], 1);
    }
}

__global__ void offsets_kernel() {
    if (threadIdx.x == 0) {
        int off = 0;
        for (int e = 0; e < EE; e++) {
            g_poff[e] = off;
            g_cur[e]  = off;
            off += ((g_cnt[e] + BM - 1) / BM) * BM;
        }
        g_poff[EE] = off;
    }
}

__global__ void scatter_kernel() {
    int idx = blockIdx.x * blockDim.x + threadIdx.x;
    if (idx >= 2 * TT) return;
    int e = g_topi[idx];
    int pos = atomicAdd(&g_cur[e], 1);
    g_rows[idx] = pos;
    g_perm[pos] = idx >> 1;
}

// ---------------- cp.async tf32 grouped GEMM ----------------
#define A_ST (BM * BK * 4)      // 16 KB
#define B_ST (BNC * BK * 4)     // 32 KB
#define STG_B (A_ST + B_ST)     // 48 KB
#define GEMM_SMEM (NS * STG_B)  // 192 KB

template <bool PHASE1>
__global__ __launch_bounds__(256, 1)
void gemm_tf32(const float* __restrict__ Bw, const float* __restrict__ bias) {
    constexpr int N = PHASE1 ? HH : DD;
    constexpr int K = PHASE1 ? DD : HH;
    constexpr int NC = K / BK;

    const int m0 = blockIdx.y * BM;
    const int n0 = blockIdx.x * BNC;
    if (m0 >= g_poff[EE]) return;
    int e = 0;
#pragma unroll
    for (int i = 0; i < EE; i++) if (m0 >= g_poff[i + 1]) e = i + 1;

    extern __shared__ char smem[];
    const uint32_t smem_base = smem_u32(smem);
    const int tid  = threadIdx.x;
    const int warp = tid >> 5, lane = tid & 31;
    const int g = lane >> 2, t = lane & 3;
    const int wr = warp >> 2, wc = warp & 3;       // 2x4 warps, 64x64 each

    // ---- copy assignments ----
    // A: row = tid&127, chunks (tid>>7)*4 + 0..3
    const int arow = tid & 127, acb = (tid >> 7) * 4;
    const float* Abase = PHASE1 ? g_Xc : g_H;
    size_t arIdx = PHASE1 ? (size_t)g_perm[m0 + arow] : (size_t)(m0 + arow);
    const char* aSrc = (const char*)(Abase + arIdx * (size_t)K) + acb * 16;
    uint32_t aDst[4];
#pragma unroll
    for (int i = 0; i < 4; i++)
        aDst[i] = arow * (BK * 4) + (((acb + i) ^ fsw(arow & 7)) << 4);
    // B: row = tid, chunks 0..7
    const char* bSrc = (const char*)(Bw + ((size_t)e * N + n0 + tid) * (size_t)K);
    uint32_t bDst[8];
#pragma unroll
    for (int i = 0; i < 8; i++)
        bDst[i] = A_ST + tid * (BK * 4) + ((i ^ fsw(tid & 7)) << 4);

    // ---- fragment read offsets ----
    const uint32_t fg = fsw((uint32_t)g);
    uint32_t ck[2] = { ((uint32_t)(t) ^ fg) << 4, ((uint32_t)(t + 4) ^ fg) << 4 };
    uint32_t aRow[4], bRow[8];
#pragma unroll
    for (int mt = 0; mt < 4; mt++) aRow[mt] = (wr * 64 + mt * 16 + g) * (BK * 4);
#pragma unroll
    for (int nt = 0; nt < 8; nt++) bRow[nt] = A_ST + (wc * 64 + nt * 8 + g) * (BK * 4);

    float acc[4][8][4];
#pragma unroll
    for (int i = 0; i < 4; i++)
#pragma unroll
        for (int j = 0; j < 8; j++)
#pragma unroll
            for (int r = 0; r < 4; r++) acc[i][j][r] = 0.f;

    auto issue = [&](int c) {
        uint32_t sb = smem_base + (c % NS) * STG_B;
        const char* as = aSrc + c * (BK * 4);
        const char* bs = bSrc + c * (BK * 4);
#pragma unroll
        for (int i = 0; i < 4; i++) cp16(sb + aDst[i], as + i * 16);
#pragma unroll
        for (int i = 0; i < 8; i++) cp16(sb + bDst[i], bs + i * 16);
    };

#pragma unroll
    for (int s = 0; s < NS - 1; s++) { issue(s); CP_COMMIT(); }

    for (int c = 0; c < NC; ++c) {
        CP_WAIT2();
        __syncthreads();
        if (c + NS - 1 < NC) issue(c + NS - 1);
        CP_COMMIT();

        const char* stg = smem + (c % NS) * STG_B;
#pragma unroll
        for (int kg = 0; kg < 2; kg++) {
            float4 al[4], ah[4];
#pragma unroll
            for (int mt = 0; mt < 4; mt++) {
                al[mt] = *(const float4*)(stg + aRow[mt] + ck[kg]);
                ah[mt] = *(const float4*)(stg + aRow[mt] + 8 * (BK * 4) + ck[kg]);
            }
#pragma unroll
            for (int h = 0; h < 2; h++) {
                float4 bf[4];
#pragma unroll
                for (int q = 0; q < 4; q++)
                    bf[q] = *(const float4*)(stg + bRow[h * 4 + q] + ck[kg]);
#pragma unroll
                for (int mt = 0; mt < 4; mt++)
#pragma unroll
                    for (int q = 0; q < 4; q++) {
                        mma_tf32(acc[mt][h * 4 + q],
                                 al[mt].x, ah[mt].x, al[mt].y, ah[mt].y, bf[q].x, bf[q].y);
                        mma_tf32(acc[mt][h * 4 + q],
                                 al[mt].z, ah[mt].z, al[mt].w, ah[mt].w, bf[q].z, bf[q].w);
                    }
            }
        }
        __syncthreads();
    }

    // ---- epilogue ----
    const float* biasp = bias + (size_t)e * N;
    if (PHASE1) {
        // gelu + rna + k-permuted scalar stores into g_H
#pragma unroll
        for (int mt = 0; mt < 4; mt++) {
            int r0 = m0 + wr * 64 + mt * 16 + g;
#pragma unroll
            for (int nt = 0; nt < 8; nt++) {
                int nb = n0 + wc * 64 + nt * 8 + 2 * t;
#pragma unroll
                for (int j = 0; j < 4; j++) {
                    int n = nb + (j & 1);
                    int row = (j < 2) ? r0 : r0 + 8;
                    float v = acc[mt][nt][j] + biasp[n];
                    v = to_tf32(gelu_exact(v));
                    int m16 = n & 15;
                    int p = (n & ~15) | (((m16 & 3) << 2) | (m16 >> 2));
                    g_H[(size_t)row * HH + p] = v;
                }
            }
        }
    } else {
#pragma unroll
        for (int mt = 0; mt < 4; mt++) {
            int r0 = m0 + wr * 64 + mt * 16 + g;
#pragma unroll
            for (int nt = 0; nt < 8; nt++) {
                int nb = n0 + wc * 64 + nt * 8 + 2 * t;
                float b0v = biasp[nb], b1v = biasp[nb + 1];
                *(float2*)&g_Y[(size_t)r0 * DD + nb] =
                    make_float2(acc[mt][nt][0] + b0v, acc[mt][nt][1] + b1v);
                *(float2*)&g_Y[(size_t)(r0 + 8) * DD + nb] =
                    make_float2(acc[mt][nt][2] + b0v, acc[mt][nt][3] + b1v);
            }
        }
    }
}

__global__ void combine_kernel(float* __restrict__ out) {
    int tk = blockIdx.x;
    int d4 = threadIdx.x;
    int r0 = g_rows[2 * tk], r1 = g_rows[2 * tk + 1];
    float w0 = g_topw[2 * tk], w1 = g_topw[2 * tk + 1];
    float4 y0 = *(const float4*)&g_Y[(size_t)r0 * DD + d4 * 4];
    float4 y1 = *(const float4*)&g_Y[(size_t)r1 * DD + d4 * 4];
    float4 o;
    o.x = w0 * y0.x + w1 * y1.x;
    o.y = w0 * y0.y + w1 * y1.y;
    o.z = w0 * y0.z + w1 * y1.z;
    o.w = w0 * y0.w + w1 * y1.w;
    ((float4*)out)[(size_t)tk * (DD / 4) + d4] = o;
}

// ---------------- launch ----------------
extern "C" void kernel_launch(void* const* d_in, const int* in_sizes, int n_in,
                              void* d_out, int out_size) {
    const float* x  = (const float*)d_in[0];
    const float* Wr = (const float*)d_in[1];
    const float* br = (const float*)d_in[2];
    const float* W1 = (const float*)d_in[3];
    const float* b1 = (const float*)d_in[4];
    const float* W2 = (const float*)d_in[5];
    const float* b2 = (const float*)d_in[6];
    float* out = (float*)d_out;
    (void)in_sizes; (void)n_in; (void)out_size;

    static int init_attr = 0;
    if (!init_attr) {
        cudaFuncSetAttribute(gemm_tf32<true>,  cudaFuncAttributeMaxDynamicSharedMemorySize, GEMM_SMEM);
        cudaFuncSetAttribute(gemm_tf32<false>, cudaFuncAttributeMaxDynamicSharedMemorySize, GEMM_SMEM);
        init_attr = 1;
    }

    float* w1c; cudaGetSymbolAddress((void**)&w1c, g_W1c);
    float* w2c; cudaGetSymbolAddress((void**)&w2c, g_W2c);

    const int wgroups = EE * HH * DD / 16;   // 2,097,152
    init_kernel<<<1, 32>>>();
    convert_permute<<<(wgroups + 255) / 256, 256>>>(W1, w1c, wgroups);
    convert_permute<<<(wgroups + 255) / 256, 256>>>(W2, w2c, wgroups);
    router_kernel<<<TT / 8, 256>>>(x, Wr, br);
    offsets_kernel<<<1, 1>>>();
    scatter_kernel<<<(2 * TT + 255) / 256, 256>>>();
    gemm_tf32<true ><<<dim3(HH / BNC, RP / BM), 256, GEMM_SMEM>>>(w1c, b1);
    gemm_tf32<false><<<dim3(DD / BNC, RP / BM), 256, GEMM_SMEM>>>(w2c, b2);
    combine_kernel<<<TT, 256>>>(out);
}